// round 13
// baseline (speedup 1.0000x reference)
#include <cuda_runtime.h>
#include <cuda_bf16.h>
#include <cstdint>

// S5 SSM scan, q-substitution + chunked two-pass form.
// R12: pass1 (F_c = G_d @ U_d, G[n][s] = a_n^{255-s}) on tensor cores:
// mma.sync m16n8k16 bf16, 3-term hi/lo split. Pass2 (FFMA2 roofline) unchanged.

#define D_MODEL   256
#define D_STATE   64
#define SEQ_LEN   4096
#define BATCH     32

#define CH        16
#define CLEN      (SEQ_LEN / CH)          // 256

#define LANES     4
#define SPL       16
#define PACKS     (SPL / 2)
#define TPB       128
#define DPB       32
#define TS        64
#define NTILES    (CLEN / TS)

typedef unsigned long long u64p;

__device__ __forceinline__ u64p pack2(float lo, float hi) {
    u64p r; asm("mov.b64 %0, {%1, %2};" : "=l"(r) : "f"(lo), "f"(hi)); return r;
}
__device__ __forceinline__ void unpack2(u64p v, float& lo, float& hi) {
    asm("mov.b64 {%0, %1}, %2;" : "=f"(lo), "=f"(hi) : "l"(v));
}
__device__ __forceinline__ u64p fma2(u64p a, u64p b, u64p c) {
    u64p d; asm("fma.rn.f32x2 %0, %1, %2, %3;" : "=l"(d) : "l"(a), "l"(b), "l"(c)); return d;
}
__device__ __forceinline__ u64p mul2(u64p a, u64p b) {
    u64p d; asm("mul.rn.f32x2 %0, %1, %2;" : "=l"(d) : "l"(a), "l"(b)); return d;
}
__device__ __forceinline__ u64p add2(u64p a, u64p b) {
    u64p d; asm("add.rn.f32x2 %0, %1, %2;" : "=l"(d) : "l"(a), "l"(b)); return d;
}
__device__ __forceinline__ uint32_t smem_u32(const void* p) {
    return (uint32_t)__cvta_generic_to_shared(p);
}
__device__ __forceinline__ void cp16(uint32_t s, const void* g) {
    asm volatile("cp.async.cg.shared.global [%0], [%1], 16;" :: "r"(s), "l"(g));
}
#define CP_COMMIT() asm volatile("cp.async.commit_group;" ::: "memory")
#define CP_WAIT0()  asm volatile("cp.async.wait_group 0;" ::: "memory")

__device__ __forceinline__ float sel4(float a0, float a1, float a2, float a3, int idx) {
    float x = (idx & 1) ? a1 : a0;
    float y = (idx & 1) ? a3 : a2;
    return (idx & 2) ? y : x;
}

__device__ __forceinline__ void mma_bf16(float* c,
    uint32_t a0, uint32_t a1, uint32_t a2, uint32_t a3, uint32_t b0, uint32_t b1)
{
    asm volatile(
        "mma.sync.aligned.m16n8k16.row.col.f32.bf16.bf16.f32 "
        "{%0,%1,%2,%3}, {%4,%5,%6,%7}, {%8,%9}, {%0,%1,%2,%3};"
        : "+f"(c[0]), "+f"(c[1]), "+f"(c[2]), "+f"(c[3])
        : "r"(a0), "r"(a1), "r"(a2), "r"(a3), "r"(b0), "r"(b1));
}

__device__ float g_a  [D_MODEL * D_STATE];
__device__ float g_aP [D_MODEL * D_STATE];
__device__ float g_cb [D_MODEL * D_STATE];
__device__ float g_q0 [D_MODEL * D_STATE];
// F layout: [d][col = b*16 + c][n]   (512 cols)
__device__ float g_F  [D_MODEL * 512 * D_STATE];
__device__ float g_Qin[BATCH * CH * D_MODEL * D_STATE];
// G in A-fragment order: [d][mt(4)][kt(16)][split(2)][lane(32)][reg(4)] as u32 bf16x2
__device__ __align__(16) uint32_t g_Gfrag[D_MODEL * 4 * 16 * 2 * 32 * 4];

__global__ void precomp_kernel(const float* __restrict__ log_dt,
                               const float* __restrict__ A_real,
                               const float* __restrict__ B,
                               const float* __restrict__ C,
                               const float* __restrict__ x0)
{
    int idx = blockIdx.x * blockDim.x + threadIdx.x;
    if (idx >= D_MODEL * D_STATE) return;
    int d = idx / D_STATE;
    float dt = expf(log_dt[d]);
    float Ar = A_real[idx];
    float ad = Ar * dt;
    float a  = expf(ad);
    float bt = (1.0f - a) * B[idx] / Ar;
    float c  = C[idx];
    float cb = c * bt;
    float p0 = c * x0[idx];
    g_a [idx] = a;
    g_aP[idx] = expf(ad * (float)CLEN);
    g_cb[idx] = cb;
    g_q0[idx] = (cb != 0.0f) ? (p0 / cb) : 0.0f;
}

// G[n][s] = a_n^{255-s}, hi/lo bf16 split, laid out as mma A-fragments.
__global__ void precomp_gfrag(const float* __restrict__ log_dt,
                              const float* __restrict__ A_real)
{
    int idx = blockIdx.x * 256 + threadIdx.x;   // 524288 threads
    int lane = idx & 31;
    int kt = (idx >> 5) & 15;
    int mt = (idx >> 9) & 3;
    int d  = idx >> 11;
    float dt = expf(log_dt[d]);
    int g = lane >> 2, tq = lane & 3;

    uint32_t hi[4], lo[4];
#pragma unroll
    for (int r = 0; r < 4; r++) {
        int n  = mt * 16 + g + 8 * (r & 1);         // a0/a2: row g ; a1/a3: row g+8
        int s0 = kt * 16 + tq * 2 + 8 * (r >> 1);   // a0/a1: k 2t ; a2/a3: k 2t+8
        float ad = A_real[d * 64 + n] * dt;
        float v0 = expf(ad * (float)(255 - s0));
        float v1 = expf(ad * (float)(255 - (s0 + 1)));
        __nv_bfloat16 h0 = __float2bfloat16(v0);
        __nv_bfloat16 h1 = __float2bfloat16(v1);
        __nv_bfloat16 l0 = __float2bfloat16(v0 - __bfloat162float(h0));
        __nv_bfloat16 l1 = __float2bfloat16(v1 - __bfloat162float(h1));
        unsigned short uh0 = *reinterpret_cast<unsigned short*>(&h0);
        unsigned short uh1 = *reinterpret_cast<unsigned short*>(&h1);
        unsigned short ul0 = *reinterpret_cast<unsigned short*>(&l0);
        unsigned short ul1 = *reinterpret_cast<unsigned short*>(&l1);
        hi[r] = (uint32_t)uh0 | ((uint32_t)uh1 << 16);
        lo[r] = (uint32_t)ul0 | ((uint32_t)ul1 << 16);
    }
    uint32_t base = ((((uint32_t)d * 4 + mt) * 16 + kt) * 2) * 128 + lane * 4;
    *reinterpret_cast<uint4*>(&g_Gfrag[base])       = make_uint4(hi[0], hi[1], hi[2], hi[3]);
    *reinterpret_cast<uint4*>(&g_Gfrag[base + 128]) = make_uint4(lo[0], lo[1], lo[2], lo[3]);
}

// ---------------- Pass 1 (tensor): F = G_d @ U_d ---------------------------
// CTA: 4 batches (64 cols) x 4 channels.  Grid = 8 * 64 = 512, 256 threads.
// Warp w -> output cols w*8..w*8+7.  M=64 states (4 mt), K=256 (16 kb).
#define SM_COLPAD 18
#define SM_PLANE  1154
__global__ void __launch_bounds__(256, 2)
pass1_mma(const float* __restrict__ u)
{
    __shared__ __align__(16) unsigned short sm_hi[4 * SM_PLANE];
    __shared__ __align__(16) unsigned short sm_lo[4 * SM_PLANE];

    int tid  = threadIdx.x;
    int lane = tid & 31;
    int w    = tid >> 5;
    int g    = lane >> 2, tq = lane & 3;

    int dg = blockIdx.x & 63;
    int bg = blockIdx.x >> 6;
    int d0 = dg * 4;

    float acc[4][4][4];
#pragma unroll
    for (int d = 0; d < 4; d++)
#pragma unroll
        for (int mt = 0; mt < 4; mt++)
#pragma unroll
            for (int r = 0; r < 4; r++) acc[d][mt][r] = 0.0f;

    int colw = w * 8 + g;

    for (int kb = 0; kb < 16; kb++) {
        __syncthreads();
        // stage 16 timesteps x 64 cols x 4 channels, fp32 -> bf16 hi/lo
#pragma unroll
        for (int i = 0; i < 4; i++) {
            int idx = tid + i * 256;
            int s   = idx & 15;
            int col = idx >> 4;
            int bq  = col >> 4, cc = col & 15;
            float4 v = *reinterpret_cast<const float4*>(
                u + ((size_t)((bg * 4 + bq) * SEQ_LEN + cc * CLEN + kb * 16 + s)) * D_MODEL + d0);
            float vv[4] = {v.x, v.y, v.z, v.w};
#pragma unroll
            for (int dl = 0; dl < 4; dl++) {
                float x = vv[dl];
                __nv_bfloat16 h = __float2bfloat16(x);
                __nv_bfloat16 l = __float2bfloat16(x - __bfloat162float(h));
                int a = dl * SM_PLANE + col * SM_COLPAD + s;
                sm_hi[a] = *reinterpret_cast<unsigned short*>(&h);
                sm_lo[a] = *reinterpret_cast<unsigned short*>(&l);
            }
        }
        __syncthreads();

#pragma unroll
        for (int d = 0; d < 4; d++) {
            int ab = d * SM_PLANE + colw * SM_COLPAD + tq * 2;
            uint32_t bh0 = *reinterpret_cast<const uint32_t*>(&sm_hi[ab]);
            uint32_t bh1 = *reinterpret_cast<const uint32_t*>(&sm_hi[ab + 8]);
            uint32_t bl0 = *reinterpret_cast<const uint32_t*>(&sm_lo[ab]);
            uint32_t bl1 = *reinterpret_cast<const uint32_t*>(&sm_lo[ab + 8]);
#pragma unroll
            for (int mt = 0; mt < 4; mt++) {
                uint32_t gb = ((((uint32_t)(d0 + d) * 4 + mt) * 16 + kb) * 2) * 128 + lane * 4;
                uint4 Ah = *reinterpret_cast<const uint4*>(&g_Gfrag[gb]);
                uint4 Al = *reinterpret_cast<const uint4*>(&g_Gfrag[gb + 128]);
                mma_bf16(acc[d][mt], Ah.x, Ah.y, Ah.z, Ah.w, bh0, bh1);
                mma_bf16(acc[d][mt], Ah.x, Ah.y, Ah.z, Ah.w, bl0, bl1);
                mma_bf16(acc[d][mt], Al.x, Al.y, Al.z, Al.w, bh0, bh1);
            }
        }
    }

    // writeback: C-frag r0:(n, col 2tq) r1:(n, 2tq+1) r2:(n+8, 2tq) r3:(n+8, 2tq+1)
    int col0 = bg * 64 + w * 8 + tq * 2;
#pragma unroll
    for (int d = 0; d < 4; d++) {
        size_t dbase = (size_t)(d0 + d) * 512;
#pragma unroll
        for (int mt = 0; mt < 4; mt++) {
            int n0 = mt * 16 + g;
            g_F[(dbase + col0)     * 64 + n0]     = acc[d][mt][0];
            g_F[(dbase + col0 + 1) * 64 + n0]     = acc[d][mt][1];
            g_F[(dbase + col0)     * 64 + n0 + 8] = acc[d][mt][2];
            g_F[(dbase + col0 + 1) * 64 + n0 + 8] = acc[d][mt][3];
        }
    }
}

// ---------------- Middle: chain Qin across chunks ---------------------------
__global__ void __launch_bounds__(256)
mid_kernel()
{
    int idx = blockIdx.x * 256 + threadIdx.x;
    int dn  = idx & (D_MODEL * D_STATE - 1);
    int b   = idx >> 14;
    int d   = dn >> 6, n = dn & 63;

    float aP = g_aP[dn];
    float q  = g_q0[dn];
    size_t stride = (size_t)D_MODEL * D_STATE;
    float* Qp = g_Qin + (size_t)b * CH * stride + dn;
    const float* Fp = g_F + ((size_t)d * 512 + b * 16) * 64 + n;

    Qp[0] = q;
#pragma unroll
    for (int c = 1; c < CH; c++) {
        q = fmaf(aP, q, Fp[(c - 1) * 64]);
        Qp[c * stride] = q;
    }
}

// ---------------- Pass 2: full scan per chunk (unchanged, at roofline) ------
__global__ void __launch_bounds__(TPB, 7)
pass2_kernel(const float* __restrict__ u, float* __restrict__ y)
{
    __shared__ float tile[2][TS * DPB];

    int tid  = threadIdx.x;
    int pl   = tid >> 2;
    int sub  = tid & (LANES - 1);
    int sub1 = sub ^ 1, sub2 = sub ^ 2, sub3 = sub ^ 3;

    int blk  = blockIdx.x;
    int dblk = blk & 7;
    int bc   = blk >> 3;
    int c    = bc & (CH - 1);
    int b    = bc >> 4;
    int d    = dblk * DPB + pl;

    u64p a2[PACKS], cba2[PACKS], q2[PACKS];
    float S = 0.0f;
    int base = d * D_STATE + sub * SPL;
    const float* Qp = g_Qin + (((size_t)b * CH + c) * D_MODEL + d) * D_STATE + sub * SPL;
#pragma unroll
    for (int i = 0; i < PACKS; i += 2) {
        float4 av  = *reinterpret_cast<const float4*>(g_a  + base + 2 * i);
        float4 cbv = *reinterpret_cast<const float4*>(g_cb + base + 2 * i);
        float4 qv  = *reinterpret_cast<const float4*>(Qp + 2 * i);
        a2 [i]    = pack2(av.x,  av.y);   a2 [i+1]  = pack2(av.z,  av.w);
        cba2[i]   = pack2(cbv.x * av.x, cbv.y * av.y);
        cba2[i+1] = pack2(cbv.z * av.z, cbv.w * av.w);
        S += (cbv.x + cbv.y) + (cbv.z + cbv.w);
        q2 [i]    = pack2(qv.x,  qv.y);   q2 [i+1]  = pack2(qv.z,  qv.w);
    }

    const float* ubase = u + ((size_t)b * SEQ_LEN + (size_t)c * CLEN) * D_MODEL + dblk * DPB;
    float*       yp    = y + ((size_t)b * SEQ_LEN + (size_t)c * CLEN) * D_MODEL + d;

#pragma unroll
    for (int k = 0; k < 4; k++) {
        int s  = tid + k * TPB;
        int tl = s >> 3, c4 = (s & 7) * 4;
        cp16(smem_u32(&tile[0][tl * DPB + c4]), ubase + tl * D_MODEL + c4);
    }
    CP_COMMIT();

    float pS = 0.0f, pS2 = 0.0f;

    for (int ct = 0; ct < NTILES; ct++) {
        CP_WAIT0();
        __syncthreads();
        if (ct + 1 < NTILES) {
            const float* src = ubase + (size_t)(ct + 1) * TS * D_MODEL;
            float* dst = tile[(ct + 1) & 1];
#pragma unroll
            for (int k = 0; k < 4; k++) {
                int s  = tid + k * TPB;
                int tl = s >> 3, c4 = (s & 7) * 4;
                cp16(smem_u32(&dst[tl * DPB + c4]), src + tl * D_MODEL + c4);
            }
            CP_COMMIT();
        }

        const float* tp = tile[ct & 1];
        float uv[2][4];
        float sA[4];

#pragma unroll
        for (int j = 0; j < 4; j++)
            uv[0][j] = tp[j * DPB + pl];

#pragma unroll
        for (int g = 0; g < TS / 4; g++) {
            int t0 = g * 4;
            float* uvC = uv[g & 1];
            float* uvN = uv[(g + 1) & 1];

            if (g + 1 < TS / 4) {
#pragma unroll
                for (int j = 0; j < 4; j++)
                    uvN[j] = tp[(t0 + 4 + j) * DPB + pl];
            }

#pragma unroll
            for (int j = 0; j < 2; j++) {
                u64p u2 = pack2(uvC[j], uvC[j]);
                u64p e = mul2(cba2[0], q2[0]);
                u64p o = mul2(cba2[1], q2[1]);
                e = fma2(cba2[2], q2[2], e);
                o = fma2(cba2[3], q2[3], o);
                e = fma2(cba2[4], q2[4], e);
                o = fma2(cba2[5], q2[5], o);
                e = fma2(cba2[6], q2[6], e);
                o = fma2(cba2[7], q2[7], o);
#pragma unroll
                for (int i = 0; i < PACKS; i++)
                    q2[i] = fma2(a2[i], q2[i], u2);
                u64p t = add2(e, o);
                float lo, hi;
                unpack2(t, lo, hi);
                sA[j] = fmaf(S, uvC[j], lo + hi);
            }

            {
                float r2  = __shfl_xor_sync(0xffffffffu, pS2, 2);
                float fin = pS + r2;
                if (ct > 0 || g > 0) {
                    int tpos = (g == 0) ? (ct * TS - 4) : (ct * TS + t0 - 4);
                    __stcs(yp + (tpos + sub) * D_MODEL, fin);
                }
            }

#pragma unroll
            for (int j = 2; j < 4; j++) {
                u64p u2 = pack2(uvC[j], uvC[j]);
                u64p e = mul2(cba2[0], q2[0]);
                u64p o = mul2(cba2[1], q2[1]);
                e = fma2(cba2[2], q2[2], e);
                o = fma2(cba2[3], q2[3], o);
                e = fma2(cba2[4], q2[4], e);
                o = fma2(cba2[5], q2[5], o);
                e = fma2(cba2[6], q2[6], e);
                o = fma2(cba2[7], q2[7], o);
#pragma unroll
                for (int i = 0; i < PACKS; i++)
                    q2[i] = fma2(a2[i], q2[i], u2);
                u64p t = add2(e, o);
                float lo, hi;
                unpack2(t, lo, hi);
                sA[j] = fmaf(S, uvC[j], lo + hi);
            }

            {
                float s1 = sel4(sA[0], sA[1], sA[2], sA[3], sub1);
                float s3 = sel4(sA[0], sA[1], sA[2], sA[3], sub3);
                float r1 = __shfl_xor_sync(0xffffffffu, s1, 1);
                float r3 = __shfl_xor_sync(0xffffffffu, s3, 1);
                float pA = sel4(sA[0], sA[1], sA[2], sA[3], sub);
                float pC = sel4(sA[0], sA[1], sA[2], sA[3], sub2);
                pS  = pA + r1;
                pS2 = pC + r3;
            }
        }
    }

    {
        float r2  = __shfl_xor_sync(0xffffffffu, pS2, 2);
        float fin = pS + r2;
        __stcs(yp + (CLEN - 4 + sub) * D_MODEL, fin);
    }
}

extern "C" void kernel_launch(void* const* d_in, const int* in_sizes, int n_in,
                              void* d_out, int out_size)
{
    const float* u      = (const float*)d_in[0];
    const float* log_dt = (const float*)d_in[1];
    const float* A_real = (const float*)d_in[2];
    const float* B      = (const float*)d_in[3];
    const float* C      = (const float*)d_in[4];
    const float* x0     = (const float*)d_in[5];
    float* y = (float*)d_out;

    precomp_kernel<<<(D_MODEL * D_STATE + 255) / 256, 256>>>(log_dt, A_real, B, C, x0);
    precomp_gfrag<<<2048, 256>>>(log_dt, A_real);

    pass1_mma<<<512, 256>>>(u);

    int mid_threads = BATCH * D_MODEL * D_STATE;
    mid_kernel<<<mid_threads / 256, 256>>>();

    int p2_blocks = BATCH * CH * (D_MODEL / DPB);
    pass2_kernel<<<p2_blocks, TPB>>>(u, y);
}

// round 15
// speedup vs baseline: 1.0156x; 1.0156x over previous
#include <cuda_runtime.h>
#include <cuda_bf16.h>
#include <cstdint>

// S5 SSM scan, q-substitution + chunked two-pass form.
// R13: pass1 on tensor cores (mma m16n8k16 bf16, 3-term hi/lo split) with
// cp.async raw staging + separate convert stage (no spills, pipelined).
// Pass2 / mid / precomp identical to the numerically verified R12.

#define D_MODEL   256
#define D_STATE   64
#define SEQ_LEN   4096
#define BATCH     32

#define CH        16
#define CLEN      (SEQ_LEN / CH)          // 256

#define LANES     4
#define SPL       16
#define PACKS     (SPL / 2)
#define TPB       128
#define DPB       32
#define TS        64
#define NTILES    (CLEN / TS)

typedef unsigned long long u64p;

__device__ __forceinline__ u64p pack2(float lo, float hi) {
    u64p r; asm("mov.b64 %0, {%1, %2};" : "=l"(r) : "f"(lo), "f"(hi)); return r;
}
__device__ __forceinline__ void unpack2(u64p v, float& lo, float& hi) {
    asm("mov.b64 {%0, %1}, %2;" : "=f"(lo), "=f"(hi) : "l"(v));
}
__device__ __forceinline__ u64p fma2(u64p a, u64p b, u64p c) {
    u64p d; asm("fma.rn.f32x2 %0, %1, %2, %3;" : "=l"(d) : "l"(a), "l"(b), "l"(c)); return d;
}
__device__ __forceinline__ u64p mul2(u64p a, u64p b) {
    u64p d; asm("mul.rn.f32x2 %0, %1, %2;" : "=l"(d) : "l"(a), "l"(b)); return d;
}
__device__ __forceinline__ u64p add2(u64p a, u64p b) {
    u64p d; asm("add.rn.f32x2 %0, %1, %2;" : "=l"(d) : "l"(a), "l"(b)); return d;
}
__device__ __forceinline__ uint32_t smem_u32(const void* p) {
    return (uint32_t)__cvta_generic_to_shared(p);
}
__device__ __forceinline__ void cp16(uint32_t s, const void* g) {
    asm volatile("cp.async.cg.shared.global [%0], [%1], 16;" :: "r"(s), "l"(g));
}
#define CP_COMMIT() asm volatile("cp.async.commit_group;" ::: "memory")
#define CP_WAIT0()  asm volatile("cp.async.wait_group 0;" ::: "memory")

__device__ __forceinline__ float sel4(float a0, float a1, float a2, float a3, int idx) {
    float x = (idx & 1) ? a1 : a0;
    float y = (idx & 1) ? a3 : a2;
    return (idx & 2) ? y : x;
}

__device__ __forceinline__ void mma_bf16(float* c,
    uint32_t a0, uint32_t a1, uint32_t a2, uint32_t a3, uint32_t b0, uint32_t b1)
{
    asm volatile(
        "mma.sync.aligned.m16n8k16.row.col.f32.bf16.bf16.f32 "
        "{%0,%1,%2,%3}, {%4,%5,%6,%7}, {%8,%9}, {%0,%1,%2,%3};"
        : "+f"(c[0]), "+f"(c[1]), "+f"(c[2]), "+f"(c[3])
        : "r"(a0), "r"(a1), "r"(a2), "r"(a3), "r"(b0), "r"(b1));
}

__device__ __forceinline__ uint32_t pkbf(__nv_bfloat16 a, __nv_bfloat16 b) {
    unsigned short ua = *reinterpret_cast<unsigned short*>(&a);
    unsigned short ub = *reinterpret_cast<unsigned short*>(&b);
    return (uint32_t)ua | ((uint32_t)ub << 16);
}

__device__ float g_a  [D_MODEL * D_STATE];
__device__ float g_aP [D_MODEL * D_STATE];
__device__ float g_cb [D_MODEL * D_STATE];
__device__ float g_q0 [D_MODEL * D_STATE];
// F layout: [d][col = b*16 + c][n]
__device__ float g_F  [D_MODEL * 512 * D_STATE];
__device__ float g_Qin[BATCH * CH * D_MODEL * D_STATE];
// G in A-fragment order
__device__ __align__(16) uint32_t g_Gfrag[D_MODEL * 4 * 16 * 2 * 32 * 4];

__global__ void precomp_kernel(const float* __restrict__ log_dt,
                               const float* __restrict__ A_real,
                               const float* __restrict__ B,
                               const float* __restrict__ C,
                               const float* __restrict__ x0)
{
    int idx = blockIdx.x * blockDim.x + threadIdx.x;
    if (idx >= D_MODEL * D_STATE) return;
    int d = idx / D_STATE;
    float dt = expf(log_dt[d]);
    float Ar = A_real[idx];
    float ad = Ar * dt;
    float a  = expf(ad);
    float bt = (1.0f - a) * B[idx] / Ar;
    float c  = C[idx];
    float cb = c * bt;
    float p0 = c * x0[idx];
    g_a [idx] = a;
    g_aP[idx] = expf(ad * (float)CLEN);
    g_cb[idx] = cb;
    g_q0[idx] = (cb != 0.0f) ? (p0 / cb) : 0.0f;
}

__global__ void precomp_gfrag(const float* __restrict__ log_dt,
                              const float* __restrict__ A_real)
{
    int idx = blockIdx.x * 256 + threadIdx.x;
    int lane = idx & 31;
    int kt = (idx >> 5) & 15;
    int mt = (idx >> 9) & 3;
    int d  = idx >> 11;
    float dt = expf(log_dt[d]);
    int g = lane >> 2, tq = lane & 3;

    uint32_t hi[4], lo[4];
#pragma unroll
    for (int r = 0; r < 4; r++) {
        int n  = mt * 16 + g + 8 * (r & 1);
        int s0 = kt * 16 + tq * 2 + 8 * (r >> 1);
        float ad = A_real[d * 64 + n] * dt;
        float v0 = expf(ad * (float)(255 - s0));
        float v1 = expf(ad * (float)(255 - (s0 + 1)));
        __nv_bfloat16 h0 = __float2bfloat16(v0);
        __nv_bfloat16 h1 = __float2bfloat16(v1);
        __nv_bfloat16 l0 = __float2bfloat16(v0 - __bfloat162float(h0));
        __nv_bfloat16 l1 = __float2bfloat16(v1 - __bfloat162float(h1));
        hi[r] = pkbf(h0, h1);
        lo[r] = pkbf(l0, l1);
    }
    uint32_t base = ((((uint32_t)d * 4 + mt) * 16 + kt) * 2) * 128 + lane * 4;
    *reinterpret_cast<uint4*>(&g_Gfrag[base])       = make_uint4(hi[0], hi[1], hi[2], hi[3]);
    *reinterpret_cast<uint4*>(&g_Gfrag[base + 128]) = make_uint4(lo[0], lo[1], lo[2], lo[3]);
}

// ---------------- Pass 1 (tensor): F = G_d @ U_d ---------------------------
// CTA: 4 channels x 64 cols, 256 threads, grid 512.
// Pipeline per kb: [wait cp(kb); sync; convert raw->bf16; sync; issue cp(kb+1);
//                   mma(kb)] — cp for kb+1 overlaps the mma section.
#define RAW_CSTR  68              // floats per col in raw buffer (16 float4 + pad)
#define SM_COLPAD 18
#define SM_PLANE  1154
__global__ void __launch_bounds__(256, 2)
pass1_mma(const float* __restrict__ u)
{
    __shared__ __align__(16) float          sm_raw[64 * RAW_CSTR];
    __shared__ __align__(16) unsigned short sm_hi [4 * SM_PLANE];
    __shared__ __align__(16) unsigned short sm_lo [4 * SM_PLANE];

    int tid  = threadIdx.x;
    int lane = tid & 31;
    int w    = tid >> 5;
    int g    = lane >> 2, tq = lane & 3;

    int dg = blockIdx.x & 63;
    int bg = blockIdx.x >> 6;
    int d0 = dg * 4;

    float acc[4][4][4];
#pragma unroll
    for (int d = 0; d < 4; d++)
#pragma unroll
        for (int mt = 0; mt < 4; mt++)
#pragma unroll
            for (int r = 0; r < 4; r++) acc[d][mt][r] = 0.0f;

    int colw = w * 8 + g;

    // cp slot mapping: idx = tid + i*256 -> s = idx&15, col = idx>>4
    // convert slot mapping: idx2 = tid + i*256 -> sp = idx2&7, col = idx2>>3 (2 slots)
    // prologue: issue kb0
    {
#pragma unroll
        for (int i = 0; i < 4; i++) {
            int idx = tid + i * 256;
            int s = idx & 15, col = idx >> 4;
            int bq = col >> 4, cc = col & 15;
            const float* src = u + ((size_t)((bg * 4 + bq) * SEQ_LEN + cc * CLEN + s)) * D_MODEL + d0;
            cp16(smem_u32(&sm_raw[col * RAW_CSTR + s * 4]), src);
        }
        CP_COMMIT();
    }

    for (int kb = 0; kb < 16; kb++) {
        CP_WAIT0();
        __syncthreads();                    // raw(kb) visible to all

        // convert raw -> bf16 hi/lo planes (2 slots per thread)
#pragma unroll
        for (int i = 0; i < 2; i++) {
            int idx = tid + i * 256;
            int sp = idx & 7, col = idx >> 3;
            float4 v0 = *reinterpret_cast<const float4*>(&sm_raw[col * RAW_CSTR + (2 * sp)     * 4]);
            float4 v1 = *reinterpret_cast<const float4*>(&sm_raw[col * RAW_CSTR + (2 * sp + 1) * 4]);
            const float* a0 = &v0.x;
            const float* a1 = &v1.x;
#pragma unroll
            for (int dl = 0; dl < 4; dl++) {
                float x0 = a0[dl], x1 = a1[dl];
                __nv_bfloat16 h0 = __float2bfloat16(x0);
                __nv_bfloat16 h1 = __float2bfloat16(x1);
                __nv_bfloat16 l0 = __float2bfloat16(x0 - __bfloat162float(h0));
                __nv_bfloat16 l1 = __float2bfloat16(x1 - __bfloat162float(h1));
                int a = dl * SM_PLANE + col * SM_COLPAD + 2 * sp;
                *reinterpret_cast<uint32_t*>(&sm_hi[a]) = pkbf(h0, h1);
                *reinterpret_cast<uint32_t*>(&sm_lo[a]) = pkbf(l0, l1);
            }
        }
        __syncthreads();                    // bf16 ready; raw free for reuse

        // issue cp for kb+1 (flows during the mma section)
        if (kb + 1 < 16) {
#pragma unroll
            for (int i = 0; i < 4; i++) {
                int idx = tid + i * 256;
                int s = idx & 15, col = idx >> 4;
                int bq = col >> 4, cc = col & 15;
                const float* src = u + ((size_t)((bg * 4 + bq) * SEQ_LEN + cc * CLEN
                                                 + (kb + 1) * 16 + s)) * D_MODEL + d0;
                cp16(smem_u32(&sm_raw[col * RAW_CSTR + s * 4]), src);
            }
            CP_COMMIT();
        }

        // mma on bf16 planes
#pragma unroll
        for (int d = 0; d < 4; d++) {
            int ab = d * SM_PLANE + colw * SM_COLPAD + tq * 2;
            uint32_t bh0 = *reinterpret_cast<const uint32_t*>(&sm_hi[ab]);
            uint32_t bh1 = *reinterpret_cast<const uint32_t*>(&sm_hi[ab + 8]);
            uint32_t bl0 = *reinterpret_cast<const uint32_t*>(&sm_lo[ab]);
            uint32_t bl1 = *reinterpret_cast<const uint32_t*>(&sm_lo[ab + 8]);
#pragma unroll
            for (int mt = 0; mt < 4; mt++) {
                uint32_t gb = ((((uint32_t)(d0 + d) * 4 + mt) * 16 + kb) * 2) * 128 + lane * 4;
                uint4 Ah = *reinterpret_cast<const uint4*>(&g_Gfrag[gb]);
                uint4 Al = *reinterpret_cast<const uint4*>(&g_Gfrag[gb + 128]);
                mma_bf16(acc[d][mt], Ah.x, Ah.y, Ah.z, Ah.w, bh0, bh1);
                mma_bf16(acc[d][mt], Ah.x, Ah.y, Ah.z, Ah.w, bl0, bl1);
                mma_bf16(acc[d][mt], Al.x, Al.y, Al.z, Al.w, bh0, bh1);
            }
        }
    }

    // writeback (layout proven in R12)
    int col0 = bg * 64 + w * 8 + tq * 2;
#pragma unroll
    for (int d = 0; d < 4; d++) {
        size_t dbase = (size_t)(d0 + d) * 512;
#pragma unroll
        for (int mt = 0; mt < 4; mt++) {
            int n0 = mt * 16 + g;
            g_F[(dbase + col0)     * 64 + n0]     = acc[d][mt][0];
            g_F[(dbase + col0 + 1) * 64 + n0]     = acc[d][mt][1];
            g_F[(dbase + col0)     * 64 + n0 + 8] = acc[d][mt][2];
            g_F[(dbase + col0 + 1) * 64 + n0 + 8] = acc[d][mt][3];
        }
    }
}

// ---------------- Middle: chain Qin across chunks ---------------------------
__global__ void __launch_bounds__(256)
mid_kernel()
{
    int idx = blockIdx.x * 256 + threadIdx.x;
    int dn  = idx & (D_MODEL * D_STATE - 1);
    int b   = idx >> 14;
    int d   = dn >> 6, n = dn & 63;

    float aP = g_aP[dn];
    float q  = g_q0[dn];
    size_t stride = (size_t)D_MODEL * D_STATE;
    float* Qp = g_Qin + (size_t)b * CH * stride + dn;
    const float* Fp = g_F + ((size_t)d * 512 + b * 16) * 64 + n;

    Qp[0] = q;
#pragma unroll
    for (int c = 1; c < CH; c++) {
        q = fmaf(aP, q, Fp[(c - 1) * 64]);
        Qp[c * stride] = q;
    }
}

// ---------------- Pass 2: full scan per chunk (unchanged, at roofline) ------
__global__ void __launch_bounds__(TPB, 7)
pass2_kernel(const float* __restrict__ u, float* __restrict__ y)
{
    __shared__ float tile[2][TS * DPB];

    int tid  = threadIdx.x;
    int pl   = tid >> 2;
    int sub  = tid & (LANES - 1);
    int sub1 = sub ^ 1, sub2 = sub ^ 2, sub3 = sub ^ 3;

    int blk  = blockIdx.x;
    int dblk = blk & 7;
    int bc   = blk >> 3;
    int c    = bc & (CH - 1);
    int b    = bc >> 4;
    int d    = dblk * DPB + pl;

    u64p a2[PACKS], cba2[PACKS], q2[PACKS];
    float S = 0.0f;
    int base = d * D_STATE + sub * SPL;
    const float* Qp = g_Qin + (((size_t)b * CH + c) * D_MODEL + d) * D_STATE + sub * SPL;
#pragma unroll
    for (int i = 0; i < PACKS; i += 2) {
        float4 av  = *reinterpret_cast<const float4*>(g_a  + base + 2 * i);
        float4 cbv = *reinterpret_cast<const float4*>(g_cb + base + 2 * i);
        float4 qv  = *reinterpret_cast<const float4*>(Qp + 2 * i);
        a2 [i]    = pack2(av.x,  av.y);   a2 [i+1]  = pack2(av.z,  av.w);
        cba2[i]   = pack2(cbv.x * av.x, cbv.y * av.y);
        cba2[i+1] = pack2(cbv.z * av.z, cbv.w * av.w);
        S += (cbv.x + cbv.y) + (cbv.z + cbv.w);
        q2 [i]    = pack2(qv.x,  qv.y);   q2 [i+1]  = pack2(qv.z,  qv.w);
    }

    const float* ubase = u + ((size_t)b * SEQ_LEN + (size_t)c * CLEN) * D_MODEL + dblk * DPB;
    float*       yp    = y + ((size_t)b * SEQ_LEN + (size_t)c * CLEN) * D_MODEL + d;

#pragma unroll
    for (int k = 0; k < 4; k++) {
        int s  = tid + k * TPB;
        int tl = s >> 3, c4 = (s & 7) * 4;
        cp16(smem_u32(&tile[0][tl * DPB + c4]), ubase + tl * D_MODEL + c4);
    }
    CP_COMMIT();

    float pS = 0.0f, pS2 = 0.0f;

    for (int ct = 0; ct < NTILES; ct++) {
        CP_WAIT0();
        __syncthreads();
        if (ct + 1 < NTILES) {
            const float* src = ubase + (size_t)(ct + 1) * TS * D_MODEL;
            float* dst = tile[(ct + 1) & 1];
#pragma unroll
            for (int k = 0; k < 4; k++) {
                int s  = tid + k * TPB;
                int tl = s >> 3, c4 = (s & 7) * 4;
                cp16(smem_u32(&dst[tl * DPB + c4]), src + tl * D_MODEL + c4);
            }
            CP_COMMIT();
        }

        const float* tp = tile[ct & 1];
        float uv[2][4];
        float sA[4];

#pragma unroll
        for (int j = 0; j < 4; j++)
            uv[0][j] = tp[j * DPB + pl];

#pragma unroll
        for (int g = 0; g < TS / 4; g++) {
            int t0 = g * 4;
            float* uvC = uv[g & 1];
            float* uvN = uv[(g + 1) & 1];

            if (g + 1 < TS / 4) {
#pragma unroll
                for (int j = 0; j < 4; j++)
                    uvN[j] = tp[(t0 + 4 + j) * DPB + pl];
            }

#pragma unroll
            for (int j = 0; j < 2; j++) {
                u64p u2 = pack2(uvC[j], uvC[j]);
                u64p e = mul2(cba2[0], q2[0]);
                u64p o = mul2(cba2[1], q2[1]);
                e = fma2(cba2[2], q2[2], e);
                o = fma2(cba2[3], q2[3], o);
                e = fma2(cba2[4], q2[4], e);
                o = fma2(cba2[5], q2[5], o);
                e = fma2(cba2[6], q2[6], e);
                o = fma2(cba2[7], q2[7], o);
#pragma unroll
                for (int i = 0; i < PACKS; i++)
                    q2[i] = fma2(a2[i], q2[i], u2);
                u64p t = add2(e, o);
                float lo, hi;
                unpack2(t, lo, hi);
                sA[j] = fmaf(S, uvC[j], lo + hi);
            }

            {
                float r2  = __shfl_xor_sync(0xffffffffu, pS2, 2);
                float fin = pS + r2;
                if (ct > 0 || g > 0) {
                    int tpos = (g == 0) ? (ct * TS - 4) : (ct * TS + t0 - 4);
                    __stcs(yp + (tpos + sub) * D_MODEL, fin);
                }
            }

#pragma unroll
            for (int j = 2; j < 4; j++) {
                u64p u2 = pack2(uvC[j], uvC[j]);
                u64p e = mul2(cba2[0], q2[0]);
                u64p o = mul2(cba2[1], q2[1]);
                e = fma2(cba2[2], q2[2], e);
                o = fma2(cba2[3], q2[3], o);
                e = fma2(cba2[4], q2[4], e);
                o = fma2(cba2[5], q2[5], o);
                e = fma2(cba2[6], q2[6], e);
                o = fma2(cba2[7], q2[7], o);
#pragma unroll
                for (int i = 0; i < PACKS; i++)
                    q2[i] = fma2(a2[i], q2[i], u2);
                u64p t = add2(e, o);
                float lo, hi;
                unpack2(t, lo, hi);
                sA[j] = fmaf(S, uvC[j], lo + hi);
            }

            {
                float s1 = sel4(sA[0], sA[1], sA[2], sA[3], sub1);
                float s3 = sel4(sA[0], sA[1], sA[2], sA[3], sub3);
                float r1 = __shfl_xor_sync(0xffffffffu, s1, 1);
                float r3 = __shfl_xor_sync(0xffffffffu, s3, 1);
                float pA = sel4(sA[0], sA[1], sA[2], sA[3], sub);
                float pC = sel4(sA[0], sA[1], sA[2], sA[3], sub2);
                pS  = pA + r1;
                pS2 = pC + r3;
            }
        }
    }

    {
        float r2  = __shfl_xor_sync(0xffffffffu, pS2, 2);
        float fin = pS + r2;
        __stcs(yp + (CLEN - 4 + sub) * D_MODEL, fin);
    }
}

extern "C" void kernel_launch(void* const* d_in, const int* in_sizes, int n_in,
                              void* d_out, int out_size)
{
    const float* u      = (const float*)d_in[0];
    const float* log_dt = (const float*)d_in[1];
    const float* A_real = (const float*)d_in[2];
    const float* B      = (const float*)d_in[3];
    const float* C      = (const float*)d_in[4];
    const float* x0     = (const float*)d_in[5];
    float* y = (float*)d_out;

    precomp_kernel<<<(D_MODEL * D_STATE + 255) / 256, 256>>>(log_dt, A_real, B, C, x0);
    precomp_gfrag<<<2048, 256>>>(log_dt, A_real);

    pass1_mma<<<512, 256>>>(u);

    int mid_threads = BATCH * D_MODEL * D_STATE;
    mid_kernel<<<mid_threads / 256, 256>>>();

    int p2_blocks = BATCH * CH * (D_MODEL / DPB);
    pass2_kernel<<<p2_blocks, TPB>>>(u, y);
}

// round 17
// speedup vs baseline: 1.4087x; 1.3870x over previous
#include <cuda_runtime.h>
#include <cstdint>

// S5 SSM scan, q-substitution + chunked two-pass form.
//   q_n[t] = a_n*q_n[t-1] + u[t],  y[t] = sum_n (cb*a)_n*q_n[t-1] + (sum cb)*u[t]
// R16: CH=4 (pass1 tax 15/16 -> 3/4; pass2 single-wave grid), mid MLP fix.
// Pass2 core identical to the verified R10 (minimal-shuffle deferred reduce).

#define D_MODEL   256
#define D_STATE   64
#define SEQ_LEN   4096
#define BATCH     32

#define CH        4
#define CLEN      (SEQ_LEN / CH)          // 1024

#define LANES     4
#define SPL       16
#define PACKS     (SPL / 2)               // 8 f32x2 packs
#define TPB       128                     // 32 pairs/block
#define DPB       32                      // d per block
#define TS        64                      // timesteps per smem tile
#define NTILES    (CLEN / TS)             // 16

typedef unsigned long long u64p;

__device__ __forceinline__ u64p pack2(float lo, float hi) {
    u64p r; asm("mov.b64 %0, {%1, %2};" : "=l"(r) : "f"(lo), "f"(hi)); return r;
}
__device__ __forceinline__ void unpack2(u64p v, float& lo, float& hi) {
    asm("mov.b64 {%0, %1}, %2;" : "=f"(lo), "=f"(hi) : "l"(v));
}
__device__ __forceinline__ u64p fma2(u64p a, u64p b, u64p c) {
    u64p d; asm("fma.rn.f32x2 %0, %1, %2, %3;" : "=l"(d) : "l"(a), "l"(b), "l"(c)); return d;
}
__device__ __forceinline__ u64p mul2(u64p a, u64p b) {
    u64p d; asm("mul.rn.f32x2 %0, %1, %2;" : "=l"(d) : "l"(a), "l"(b)); return d;
}
__device__ __forceinline__ u64p add2(u64p a, u64p b) {
    u64p d; asm("add.rn.f32x2 %0, %1, %2;" : "=l"(d) : "l"(a), "l"(b)); return d;
}
__device__ __forceinline__ uint32_t smem_u32(const void* p) {
    return (uint32_t)__cvta_generic_to_shared(p);
}
__device__ __forceinline__ void cp16(uint32_t s, const void* g) {
    asm volatile("cp.async.cg.shared.global [%0], [%1], 16;" :: "r"(s), "l"(g));
}
#define CP_COMMIT() asm volatile("cp.async.commit_group;" ::: "memory")
#define CP_WAIT0()  asm volatile("cp.async.wait_group 0;" ::: "memory")

// 4-way select (ALU pipe SELs)
__device__ __forceinline__ float sel4(float a0, float a1, float a2, float a3, int idx) {
    float x = (idx & 1) ? a1 : a0;
    float y = (idx & 1) ? a3 : a2;
    return (idx & 2) ? y : x;
}

__device__ float g_a  [D_MODEL * D_STATE];
__device__ float g_aP [D_MODEL * D_STATE];
__device__ float g_cb [D_MODEL * D_STATE];
__device__ float g_q0 [D_MODEL * D_STATE];
__device__ float g_F  [BATCH * CH * D_MODEL * D_STATE];
__device__ float g_Qin[BATCH * CH * D_MODEL * D_STATE];

__global__ void precomp_kernel(const float* __restrict__ log_dt,
                               const float* __restrict__ A_real,
                               const float* __restrict__ B,
                               const float* __restrict__ C,
                               const float* __restrict__ x0)
{
    int idx = blockIdx.x * blockDim.x + threadIdx.x;
    if (idx >= D_MODEL * D_STATE) return;
    int d = idx / D_STATE;
    float dt = expf(log_dt[d]);
    float Ar = A_real[idx];
    float ad = Ar * dt;
    float a  = expf(ad);
    float bt = (1.0f - a) * B[idx] / Ar;
    float c  = C[idx];
    float cb = c * bt;
    float p0 = c * x0[idx];
    g_a [idx] = a;
    g_aP[idx] = expf(ad * (float)CLEN);
    g_cb[idx] = cb;
    g_q0[idx] = (cb != 0.0f) ? (p0 / cb) : 0.0f;
}

// ---------------- Pass 1: chunk-local finals (recurrence only) --------------
// Tasks: (b, c=0..CH-2, d-block).  Grid = 32 * 3 * 8 = 768 blocks.
__global__ void __launch_bounds__(TPB, 8)
pass1_kernel(const float* __restrict__ u)
{
    __shared__ float tile[2][TS * DPB];

    int tid  = threadIdx.x;
    int pl   = tid >> 2;
    int sub  = tid & (LANES - 1);

    int blk  = blockIdx.x;
    int dblk = blk & 7;
    int bc   = blk >> 3;
    int c    = bc % (CH - 1);
    int b    = bc / (CH - 1);
    int d    = dblk * DPB + pl;

    u64p a2[PACKS], q2[PACKS];
    int base = d * D_STATE + sub * SPL;
#pragma unroll
    for (int i = 0; i < PACKS; i += 2) {
        float4 av = *reinterpret_cast<const float4*>(g_a + base + 2 * i);
        a2[i]   = pack2(av.x, av.y);
        a2[i+1] = pack2(av.z, av.w);
        q2[i]   = 0ull;
        q2[i+1] = 0ull;
    }

    const float* ubase = u + ((size_t)b * SEQ_LEN + (size_t)c * CLEN) * D_MODEL + dblk * DPB;

#pragma unroll
    for (int k = 0; k < 4; k++) {
        int s  = tid + k * TPB;
        int tl = s >> 3, c4 = (s & 7) * 4;
        cp16(smem_u32(&tile[0][tl * DPB + c4]), ubase + tl * D_MODEL + c4);
    }
    CP_COMMIT();

    for (int ct = 0; ct < NTILES; ct++) {
        CP_WAIT0();
        __syncthreads();
        if (ct + 1 < NTILES) {
            const float* src = ubase + (size_t)(ct + 1) * TS * D_MODEL;
            float* dst = tile[(ct + 1) & 1];
#pragma unroll
            for (int k = 0; k < 4; k++) {
                int s  = tid + k * TPB;
                int tl = s >> 3, c4 = (s & 7) * 4;
                cp16(smem_u32(&dst[tl * DPB + c4]), src + tl * D_MODEL + c4);
            }
            CP_COMMIT();
        }

        const float* tp = tile[ct & 1];
        float uv[2][8];
#pragma unroll
        for (int j = 0; j < 8; j++)
            uv[0][j] = tp[j * DPB + pl];

#pragma unroll
        for (int g = 0; g < TS / 8; g++) {
            int t0 = g * 8;
            float* uvC = uv[g & 1];
            float* uvN = uv[(g + 1) & 1];
            if (g + 1 < TS / 8) {
#pragma unroll
                for (int j = 0; j < 8; j++)
                    uvN[j] = tp[(t0 + 8 + j) * DPB + pl];
            }
#pragma unroll
            for (int j = 0; j < 8; j++) {
                u64p u2 = pack2(uvC[j], uvC[j]);
#pragma unroll
                for (int i = 0; i < PACKS; i++)
                    q2[i] = fma2(a2[i], q2[i], u2);
            }
        }
    }

    float* Fp = g_F + (((size_t)b * CH + c) * D_MODEL + d) * D_STATE + sub * SPL;
#pragma unroll
    for (int i = 0; i < PACKS; i += 2) {
        float4 v;
        unpack2(q2[i],   v.x, v.y);
        unpack2(q2[i+1], v.z, v.w);
        *reinterpret_cast<float4*>(Fp + 2 * i) = v;
    }
}

// ---------------- Middle: chain Qin across chunks (MLP-batched) -------------
__global__ void __launch_bounds__(256)
mid_kernel()
{
    int idx = blockIdx.x * 256 + threadIdx.x;
    int dn  = idx & (D_MODEL * D_STATE - 1);
    int b   = idx >> 14;

    size_t stride = (size_t)D_MODEL * D_STATE;
    const float* Fp = g_F + (size_t)b * CH * stride + dn;
    float* Qp = g_Qin + (size_t)b * CH * stride + dn;

    // independent upfront loads (MLP = CH-1), then short Horner chain
    float f[CH - 1];
#pragma unroll
    for (int c = 0; c < CH - 1; c++)
        f[c] = Fp[(size_t)c * stride];

    float aP = g_aP[dn];
    float q  = g_q0[dn];
    Qp[0] = q;
#pragma unroll
    for (int c = 1; c < CH; c++) {
        q = fmaf(aP, q, f[c - 1]);
        Qp[(size_t)c * stride] = q;
    }
}

// ---------------- Pass 2: full scan per chunk -------------------------------
// Grid = 32 * 4 * 8 = 1024 blocks = exactly one wave at 7 CTAs/SM.
__global__ void __launch_bounds__(TPB, 7)
pass2_kernel(const float* __restrict__ u, float* __restrict__ y)
{
    __shared__ float tile[2][TS * DPB];

    int tid  = threadIdx.x;
    int pl   = tid >> 2;
    int sub  = tid & (LANES - 1);
    int sub1 = sub ^ 1, sub2 = sub ^ 2, sub3 = sub ^ 3;

    int blk  = blockIdx.x;
    int dblk = blk & 7;
    int bc   = blk >> 3;
    int c    = bc & (CH - 1);
    int b    = bc >> 2;
    int d    = dblk * DPB + pl;

    u64p a2[PACKS], cba2[PACKS], q2[PACKS];
    float S = 0.0f;
    int base = d * D_STATE + sub * SPL;
    const float* Qp = g_Qin + (((size_t)b * CH + c) * D_MODEL + d) * D_STATE + sub * SPL;
#pragma unroll
    for (int i = 0; i < PACKS; i += 2) {
        float4 av  = *reinterpret_cast<const float4*>(g_a  + base + 2 * i);
        float4 cbv = *reinterpret_cast<const float4*>(g_cb + base + 2 * i);
        float4 qv  = *reinterpret_cast<const float4*>(Qp + 2 * i);
        a2 [i]    = pack2(av.x,  av.y);   a2 [i+1]  = pack2(av.z,  av.w);
        cba2[i]   = pack2(cbv.x * av.x, cbv.y * av.y);
        cba2[i+1] = pack2(cbv.z * av.z, cbv.w * av.w);
        S += (cbv.x + cbv.y) + (cbv.z + cbv.w);
        q2 [i]    = pack2(qv.x,  qv.y);   q2 [i+1]  = pack2(qv.z,  qv.w);
    }

    const float* ubase = u + ((size_t)b * SEQ_LEN + (size_t)c * CLEN) * D_MODEL + dblk * DPB;
    float*       yp    = y + ((size_t)b * SEQ_LEN + (size_t)c * CLEN) * D_MODEL + d;

#pragma unroll
    for (int k = 0; k < 4; k++) {
        int s  = tid + k * TPB;
        int tl = s >> 3, c4 = (s & 7) * 4;
        cp16(smem_u32(&tile[0][tl * DPB + c4]), ubase + tl * D_MODEL + c4);
    }
    CP_COMMIT();

    // carried pair-sums: pS = pairSum(timestep sub), pS2 = pairSum(timestep sub^2)
    float pS = 0.0f, pS2 = 0.0f;

    for (int ct = 0; ct < NTILES; ct++) {
        CP_WAIT0();
        __syncthreads();
        if (ct + 1 < NTILES) {
            const float* src = ubase + (size_t)(ct + 1) * TS * D_MODEL;
            float* dst = tile[(ct + 1) & 1];
#pragma unroll
            for (int k = 0; k < 4; k++) {
                int s  = tid + k * TPB;
                int tl = s >> 3, c4 = (s & 7) * 4;
                cp16(smem_u32(&dst[tl * DPB + c4]), src + tl * D_MODEL + c4);
            }
            CP_COMMIT();
        }

        const float* tp = tile[ct & 1];
        float uv[2][4];
        float sA[4];

#pragma unroll
        for (int j = 0; j < 4; j++)
            uv[0][j] = tp[j * DPB + pl];

#pragma unroll
        for (int g = 0; g < TS / 4; g++) {
            int t0 = g * 4;
            float* uvC = uv[g & 1];
            float* uvN = uv[(g + 1) & 1];

            // (a) LDS next group (latency hidden by compute)
            if (g + 1 < TS / 4) {
#pragma unroll
                for (int j = 0; j < 4; j++)
                    uvN[j] = tp[(t0 + 4 + j) * DPB + pl];
            }

            // (b) compute steps 0,1
#pragma unroll
            for (int j = 0; j < 2; j++) {
                u64p u2 = pack2(uvC[j], uvC[j]);
                u64p e = mul2(cba2[0], q2[0]);
                u64p o = mul2(cba2[1], q2[1]);
                e = fma2(cba2[2], q2[2], e);
                o = fma2(cba2[3], q2[3], o);
                e = fma2(cba2[4], q2[4], e);
                o = fma2(cba2[5], q2[5], o);
                e = fma2(cba2[6], q2[6], e);
                o = fma2(cba2[7], q2[7], o);
#pragma unroll
                for (int i = 0; i < PACKS; i++)
                    q2[i] = fma2(a2[i], q2[i], u2);
                u64p t = add2(e, o);
                float lo, hi;
                unpack2(t, lo, hi);
                sA[j] = fmaf(S, uvC[j], lo + hi);
            }

            // (c) deferred stage-2 for previous group: 1 shfl
            {
                float r2  = __shfl_xor_sync(0xffffffffu, pS2, 2);
                float fin = pS + r2;
                if (ct > 0 || g > 0) {
                    int tpos = (g == 0) ? (ct * TS - 4) : (ct * TS + t0 - 4);
                    __stcs(yp + (tpos + sub) * D_MODEL, fin);
                }
            }

            // (d) compute steps 2,3
#pragma unroll
            for (int j = 2; j < 4; j++) {
                u64p u2 = pack2(uvC[j], uvC[j]);
                u64p e = mul2(cba2[0], q2[0]);
                u64p o = mul2(cba2[1], q2[1]);
                e = fma2(cba2[2], q2[2], e);
                o = fma2(cba2[3], q2[3], o);
                e = fma2(cba2[4], q2[4], e);
                o = fma2(cba2[5], q2[5], o);
                e = fma2(cba2[6], q2[6], e);
                o = fma2(cba2[7], q2[7], o);
#pragma unroll
                for (int i = 0; i < PACKS; i++)
                    q2[i] = fma2(a2[i], q2[i], u2);
                u64p t = add2(e, o);
                float lo, hi;
                unpack2(t, lo, hi);
                sA[j] = fmaf(S, uvC[j], lo + hi);
            }

            // (e) stage-1: 2 shfls
            {
                float s1 = sel4(sA[0], sA[1], sA[2], sA[3], sub1);
                float s3 = sel4(sA[0], sA[1], sA[2], sA[3], sub3);
                float r1 = __shfl_xor_sync(0xffffffffu, s1, 1);
                float r3 = __shfl_xor_sync(0xffffffffu, s3, 1);
                float pA = sel4(sA[0], sA[1], sA[2], sA[3], sub);
                float pC = sel4(sA[0], sA[1], sA[2], sA[3], sub2);
                pS  = pA + r1;
                pS2 = pC + r3;
            }
        }
    }

    // epilogue: stage-2 + store for the final group
    {
        float r2  = __shfl_xor_sync(0xffffffffu, pS2, 2);
        float fin = pS + r2;
        __stcs(yp + (CLEN - 4 + sub) * D_MODEL, fin);
    }
}

extern "C" void kernel_launch(void* const* d_in, const int* in_sizes, int n_in,
                              void* d_out, int out_size)
{
    // metadata order: u, log_dt, A_real, B, C, x0
    const float* u      = (const float*)d_in[0];
    const float* log_dt = (const float*)d_in[1];
    const float* A_real = (const float*)d_in[2];
    const float* B      = (const float*)d_in[3];
    const float* C      = (const float*)d_in[4];
    const float* x0     = (const float*)d_in[5];
    float* y = (float*)d_out;

    precomp_kernel<<<(D_MODEL * D_STATE + 255) / 256, 256>>>(log_dt, A_real, B, C, x0);

    int p1_blocks = BATCH * (CH - 1) * (D_MODEL / DPB);    // 768
    pass1_kernel<<<p1_blocks, TPB>>>(u);

    int mid_threads = BATCH * D_MODEL * D_STATE;           // 524288
    mid_kernel<<<mid_threads / 256, 256>>>();

    int p2_blocks = BATCH * CH * (D_MODEL / DPB);          // 1024
    pass2_kernel<<<p2_blocks, TPB>>>(u, y);
}